// round 15
// baseline (speedup 1.0000x reference)
#include <cuda_runtime.h>
#include <cuda_fp16.h>
#include <cstdint>

#define B_ 4
#define T_ 1024
#define E_ 512
#define H_ 64
#define DK 8

typedef unsigned long long ull;

__device__ float g_attn[B_ * T_ * E_];

__device__ __forceinline__ uint32_t h2p(float lo, float hi) {
    uint32_t r;
    asm("cvt.rn.f16x2.f32 %0, %1, %2;" : "=r"(r) : "f"(hi), "f"(lo));
    return r;
}
__device__ __forceinline__ uint32_t ex2h2(uint32_t s) {
    uint32_t r;
    asm("ex2.approx.f16x2 %0, %1;" : "=r"(r) : "r"(s));
    return r;
}
__device__ __forceinline__ uint32_t hadd2(uint32_t a, uint32_t b) {
    uint32_t r;
    asm("add.f16x2 %0, %1, %2;" : "=r"(r) : "r"(a), "r"(b));
    return r;
}
__device__ __forceinline__ uint32_t tf32r(float f) {
    uint32_t u;
    asm("cvt.rna.tf32.f32 %0, %1;" : "=r"(u) : "f"(f));
    return u;
}
__device__ __forceinline__ uint32_t smem_u32(const void* p) {
    uint32_t a;
    asm("{ .reg .u64 t; cvta.to.shared.u64 t, %1; cvt.u32.u64 %0, t; }" : "=r"(a) : "l"(p));
    return a;
}
__device__ __forceinline__ void ldsm_x2(uint32_t& r0, uint32_t& r1, uint32_t a) {
    asm volatile("ldmatrix.sync.aligned.m8n8.x2.shared.b16 {%0,%1}, [%2];"
                 : "=r"(r0), "=r"(r1) : "r"(a));
}
__device__ __forceinline__ void ldsm_x2t(uint32_t& r0, uint32_t& r1, uint32_t a) {
    asm volatile("ldmatrix.sync.aligned.m8n8.x2.trans.shared.b16 {%0,%1}, [%2];"
                 : "=r"(r0), "=r"(r1) : "r"(a));
}
__device__ __forceinline__ void mma_k8h(float c[4], uint32_t a0, uint32_t a1, uint32_t b0) {
    asm volatile("mma.sync.aligned.m16n8k8.row.col.f32.f16.f16.f32 "
                 "{%0,%1,%2,%3}, {%4,%5}, {%6}, {%0,%1,%2,%3};"
                 : "+f"(c[0]), "+f"(c[1]), "+f"(c[2]), "+f"(c[3])
                 : "r"(a0), "r"(a1), "r"(b0));
}
__device__ __forceinline__ void mma_k16h(float c[4], uint32_t a0, uint32_t a1,
                                         uint32_t a2, uint32_t a3,
                                         uint32_t b0, uint32_t b1) {
    asm volatile("mma.sync.aligned.m16n8k16.row.col.f32.f16.f16.f32 "
                 "{%0,%1,%2,%3}, {%4,%5,%6,%7}, {%8,%9}, {%0,%1,%2,%3};"
                 : "+f"(c[0]), "+f"(c[1]), "+f"(c[2]), "+f"(c[3])
                 : "r"(a0), "r"(a1), "r"(a2), "r"(a3), "r"(b0), "r"(b1));
}
__device__ __forceinline__ void mma_tf32(float c[4], uint32_t a0, uint32_t a1,
                                         uint32_t a2, uint32_t a3,
                                         uint32_t b0, uint32_t b1) {
    asm volatile("mma.sync.aligned.m16n8k8.row.col.f32.tf32.tf32.f32 "
                 "{%0,%1,%2,%3}, {%4,%5,%6,%7}, {%8,%9}, {%0,%1,%2,%3};"
                 : "+f"(c[0]), "+f"(c[1]), "+f"(c[2]), "+f"(c[3])
                 : "r"(a0), "r"(a1), "r"(a2), "r"(a3), "r"(b0), "r"(b1));
}

// ============================================================================
// Kernel 1: tensor-core attention, f16 datapath (R14 structure) with:
//  - __launch_bounds__(256, 3): 6 warps/SMSP to hide the LDSM->MMA->EX2 chain
//    (R14 showed it's latency-bound at occ 2, not MUFU-throughput bound).
//  - Row-sums accumulated in packed f16x2 over 8-iter blocks (4 hadd2/iter
//    replaces hadd2+cvt+4 f32 adds; block flush to f32 keeps precision).
// ============================================================================
__global__ __launch_bounds__(256, 3)
void qattn_mma(const float* __restrict__ x, const float* __restrict__ theta) {
    __shared__ __align__(16) __half Ps[T_][DK];
    __shared__ __align__(16) __half Pv[T_][DK];
    __shared__ float cth[DK];

    const int tid  = threadIdx.x;
    const int lane = tid & 31;
    const int warp = tid >> 5;
    const int qt   = blockIdx.x & 7;
    const int bh   = blockIdx.x >> 3;
    const int b    = bh >> 6;
    const int h    = bh & 63;

    if (tid < DK) cth[tid] = __cosf(theta[tid]);
    __syncthreads();

    const float S1 = 0.714215694f;  // sqrt((1/sqrt(8)) * log2(e))
    const float* xb = x + ((size_t)b * T_) * E_ + h * DK;
    #pragma unroll
    for (int i = 0; i < 4; i++) {
        int t = i * 256 + tid;
        float4 v0 = *(const float4*)(xb + (size_t)t * E_);
        float4 v1 = *(const float4*)(xb + (size_t)t * E_ + 4);
        float c[8];
        c[0] = __cosf(v0.x) * cth[0]; c[1] = __cosf(v0.y) * cth[1];
        c[2] = __cosf(v0.z) * cth[2]; c[3] = __cosf(v0.w) * cth[3];
        c[4] = __cosf(v1.x) * cth[4]; c[5] = __cosf(v1.y) * cth[5];
        c[6] = __cosf(v1.z) * cth[6]; c[7] = __cosf(v1.w) * cth[7];
        uint4 ps, pv;
        ps.x = h2p(S1 * c[0], S1 * c[1]); ps.y = h2p(S1 * c[2], S1 * c[3]);
        ps.z = h2p(S1 * c[4], S1 * c[5]); ps.w = h2p(S1 * c[6], S1 * c[7]);
        pv.x = h2p(c[0], c[1]); pv.y = h2p(c[2], c[3]);
        pv.z = h2p(c[4], c[5]); pv.w = h2p(c[6], c[7]);
        *(uint4*)&Ps[t][0] = ps;
        *(uint4*)&Pv[t][0] = pv;
    }
    __syncthreads();

    const int qbase = qt * 128 + warp * 16;
    uint32_t qa0, qa1;
    ldsm_x2(qa0, qa1, smem_u32(&Ps[qbase + (lane & 15)][0]));

    float o[4] = {0.f, 0.f, 0.f, 0.f};
    float l0 = 0.f, l1 = 0.f;

    for (int blk = 0; blk < 8; blk++) {
        uint32_t lh0 = 0u, lh1 = 0u;   // packed f16x2 row-sum accumulators
        #pragma unroll
        for (int it = 0; it < 8; it++) {
            const int k0 = (blk * 8 + it) * 16;
            uint32_t kb0, kb1, vb0, vb1;
            ldsm_x2(kb0, kb1, smem_u32(&Ps[k0 + (lane & 15)][0]));
            ldsm_x2t(vb0, vb1, smem_u32(&Pv[k0 + (lane & 15)][0]));

            float c0[4] = {0.f, 0.f, 0.f, 0.f};
            float c1[4] = {0.f, 0.f, 0.f, 0.f};
            mma_k8h(c0, qa0, qa1, kb0);   // keys k0..k0+7
            mma_k8h(c1, qa0, qa1, kb1);   // keys k0+8..k0+15

            // scores -> f16x2 -> 2-wide EX2: results ARE the PV A-fragment.
            uint32_t p0 = ex2h2(h2p(c0[0], c0[1]));   // row r
            uint32_t p1 = ex2h2(h2p(c0[2], c0[3]));   // row r+8
            uint32_t p2 = ex2h2(h2p(c1[0], c1[1]));   // row r
            uint32_t p3 = ex2h2(h2p(c1[2], c1[3]));   // row r+8

            lh0 = hadd2(lh0, p0); lh0 = hadd2(lh0, p2);
            lh1 = hadd2(lh1, p1); lh1 = hadd2(lh1, p3);

            mma_k16h(o, p0, p1, p2, p3, vb0, vb1);
        }
        // Flush block sums to f32 (per-half max 16*17 = 272, safe in f16).
        float2 f0 = __half22float2(*(__half2*)&lh0);
        float2 f1 = __half22float2(*(__half2*)&lh1);
        l0 += f0.x + f0.y;
        l1 += f1.x + f1.y;
    }

    l0 += __shfl_xor_sync(0xFFFFFFFFu, l0, 1);
    l0 += __shfl_xor_sync(0xFFFFFFFFu, l0, 2);
    l1 += __shfl_xor_sync(0xFFFFFFFFu, l1, 1);
    l1 += __shfl_xor_sync(0xFFFFFFFFu, l1, 2);
    float inv0 = 1.0f / l0, inv1 = 1.0f / l1;

    const int q0 = qbase + (lane >> 2);
    const int col = h * DK + ((lane & 3) << 1);
    float* p0o = g_attn + ((size_t)(b * T_ + q0)) * E_ + col;
    float* p1o = g_attn + ((size_t)(b * T_ + q0 + 8)) * E_ + col;
    *(float2*)p0o = make_float2(o[0] * inv0, o[1] * inv0);
    *(float2*)p1o = make_float2(o[2] * inv1, o[3] * inv1);
}

// ============================================================================
// Kernel 2: tf32 combine GEMM — EXACT R10 body (proven 33.2us best).
// ============================================================================
#define PA_SZ 3328   // 8 mb * 2 kb * 208
#define PB_SZ 1088   // 8 nb * 2 kb * 68
__global__ __launch_bounds__(256)
void combine_tf32(const float* __restrict__ W, const float* __restrict__ bias,
                  float* __restrict__ C) {
    __shared__ __align__(16) uint32_t PA[2][PA_SZ];
    __shared__ __align__(16) uint32_t PB[2][PB_SZ];

    const int tid  = threadIdx.x;
    const int lane = tid & 31;
    const int warp = tid >> 5;
    const int g    = lane >> 2;
    const int tg   = lane & 3;
    const int row0 = blockIdx.y * 128;
    const int col0 = blockIdx.x * 64;
    const int mw   = warp >> 1;
    const int nw   = warp & 1;

    const int ar = tid >> 1, akb = tid & 1;
    const int wr = tid >> 2, wq = tid & 3;
    const int wkb = wq >> 1, wsel = wq & 1;
    const float* Ap = g_attn + (size_t)(row0 + ar) * E_ + akb * 8;
    const float* Wp = W      + (size_t)(col0 + wr) * E_ + wq * 4;

    const int a_base = ((ar >> 4) * 2 + akb) * 208 + ((ar >> 3) & 1) + (ar & 7) * 2;
    const int w_base = ((wr >> 3) * 2 + wkb) * 68 + (wr & 7) * 8 + wsel;

    float acc[2][4][4];
    #pragma unroll
    for (int mi = 0; mi < 2; mi++)
        #pragma unroll
        for (int ni = 0; ni < 4; ni++)
            #pragma unroll
            for (int j = 0; j < 4; j++) acc[mi][ni][j] = 0.f;

    float4 ra0 = *(const float4*)(Ap);
    float4 ra1 = *(const float4*)(Ap + 4);
    float4 rw  = *(const float4*)(Wp);

    {
        float av[8] = {ra0.x, ra0.y, ra0.z, ra0.w, ra1.x, ra1.y, ra1.z, ra1.w};
        #pragma unroll
        for (int j = 0; j < 8; j++) PA[0][a_base + j * 24] = tf32r(av[j]);
        float wv[4] = {rw.x, rw.y, rw.z, rw.w};
        #pragma unroll
        for (int j = 0; j < 4; j++) PB[0][w_base + j * 2] = tf32r(wv[j]);
    }
    __syncthreads();

    for (int ch = 0; ch < E_ / 16; ch++) {
        const int buf = ch & 1;
        const bool more = (ch + 1) < E_ / 16;
        if (more) {
            ra0 = *(const float4*)(Ap + (ch + 1) * 16);
            ra1 = *(const float4*)(Ap + (ch + 1) * 16 + 4);
            rw  = *(const float4*)(Wp + (ch + 1) * 16);
        }

        const uint32_t* pa = PA[buf];
        const uint32_t* pb = PB[buf];
        #pragma unroll
        for (int kb = 0; kb < 2; kb++) {
            ull ap1[2], ap2[2], bp[4];
            #pragma unroll
            for (int mi = 0; mi < 2; mi++) {
                int ab = ((2 * mw + mi) * 2 + kb) * 208 + tg * 24 + g * 2;
                ap1[mi] = *(const ull*)&pa[ab];
                ap2[mi] = *(const ull*)&pa[ab + 96];
            }
            #pragma unroll
            for (int ni = 0; ni < 4; ni++) {
                int bb = ((4 * nw + ni) * 2 + kb) * 68 + g * 8 + tg * 2;
                bp[ni] = *(const ull*)&pb[bb];
            }
            #pragma unroll
            for (int ni = 0; ni < 4; ni++) {
                uint32_t b0 = (uint32_t)bp[ni], b1 = (uint32_t)(bp[ni] >> 32);
                #pragma unroll
                for (int mi = 0; mi < 2; mi++) {
                    uint32_t a0 = (uint32_t)ap1[mi], a1 = (uint32_t)(ap1[mi] >> 32);
                    uint32_t a2 = (uint32_t)ap2[mi], a3 = (uint32_t)(ap2[mi] >> 32);
                    mma_tf32(acc[mi][ni], a0, a1, a2, a3, b0, b1);
                }
            }
        }

        if (more) {
            const int nb = buf ^ 1;
            float av[8] = {ra0.x, ra0.y, ra0.z, ra0.w, ra1.x, ra1.y, ra1.z, ra1.w};
            #pragma unroll
            for (int j = 0; j < 8; j++) PA[nb][a_base + j * 24] = tf32r(av[j]);
            float wv[4] = {rw.x, rw.y, rw.z, rw.w};
            #pragma unroll
            for (int j = 0; j < 4; j++) PB[nb][w_base + j * 2] = tf32r(wv[j]);
        }
        __syncthreads();
    }

    #pragma unroll
    for (int mi = 0; mi < 2; mi++) {
        int row = row0 + mw * 32 + mi * 16 + g;
        #pragma unroll
        for (int ni = 0; ni < 4; ni++) {
            int c = col0 + nw * 32 + ni * 8 + (tg << 1);
            float2 bi = *(const float2*)&bias[c];
            *(float2*)&C[(size_t)row * E_ + c] =
                make_float2(acc[mi][ni][0] + bi.x, acc[mi][ni][1] + bi.y);
            *(float2*)&C[(size_t)(row + 8) * E_ + c] =
                make_float2(acc[mi][ni][2] + bi.x, acc[mi][ni][3] + bi.y);
        }
    }
}

extern "C" void kernel_launch(void* const* d_in, const int* in_sizes, int n_in,
                              void* d_out, int out_size) {
    const float* x     = (const float*)d_in[0];
    const float* theta = (const float*)d_in[1];
    const float* W     = (const float*)d_in[2];
    const float* bias  = (const float*)d_in[3];
    float* out = (float*)d_out;

    qattn_mma<<<B_ * H_ * 8, 256>>>(x, theta);
    dim3 g2(E_ / 64, (B_ * T_) / 128);
    combine_tf32<<<g2, 256>>>(W, bias, out);
}

// round 16
// speedup vs baseline: 1.1760x; 1.1760x over previous
#include <cuda_runtime.h>
#include <cuda_fp16.h>
#include <cstdint>

#define B_ 4
#define T_ 1024
#define E_ 512
#define H_ 64
#define DK 8

typedef unsigned long long ull;

__device__ float g_attn[B_ * T_ * E_];

__device__ __forceinline__ uint32_t h2p(float lo, float hi) {
    uint32_t r;
    asm("cvt.rn.f16x2.f32 %0, %1, %2;" : "=r"(r) : "f"(hi), "f"(lo));
    return r;
}
__device__ __forceinline__ uint32_t ex2h2(uint32_t s) {
    uint32_t r;
    asm("ex2.approx.f16x2 %0, %1;" : "=r"(r) : "r"(s));
    return r;
}
__device__ __forceinline__ uint32_t hadd2(uint32_t a, uint32_t b) {
    uint32_t r;
    asm("add.f16x2 %0, %1, %2;" : "=r"(r) : "r"(a), "r"(b));
    return r;
}
__device__ __forceinline__ uint32_t tf32r(float f) {
    uint32_t u;
    asm("cvt.rna.tf32.f32 %0, %1;" : "=r"(u) : "f"(f));
    return u;
}
__device__ __forceinline__ uint32_t smem_u32(const void* p) {
    uint32_t a;
    asm("{ .reg .u64 t; cvta.to.shared.u64 t, %1; cvt.u32.u64 %0, t; }" : "=r"(a) : "l"(p));
    return a;
}
__device__ __forceinline__ void ldsm_x2(uint32_t& r0, uint32_t& r1, uint32_t a) {
    asm volatile("ldmatrix.sync.aligned.m8n8.x2.shared.b16 {%0,%1}, [%2];"
                 : "=r"(r0), "=r"(r1) : "r"(a));
}
__device__ __forceinline__ void ldsm_x2t(uint32_t& r0, uint32_t& r1, uint32_t a) {
    asm volatile("ldmatrix.sync.aligned.m8n8.x2.trans.shared.b16 {%0,%1}, [%2];"
                 : "=r"(r0), "=r"(r1) : "r"(a));
}
__device__ __forceinline__ void mma_k8h(float c[4], uint32_t a0, uint32_t a1, uint32_t b0) {
    asm volatile("mma.sync.aligned.m16n8k8.row.col.f32.f16.f16.f32 "
                 "{%0,%1,%2,%3}, {%4,%5}, {%6}, {%0,%1,%2,%3};"
                 : "+f"(c[0]), "+f"(c[1]), "+f"(c[2]), "+f"(c[3])
                 : "r"(a0), "r"(a1), "r"(b0));
}
__device__ __forceinline__ void mma_k16h(float c[4], uint32_t a0, uint32_t a1,
                                         uint32_t a2, uint32_t a3,
                                         uint32_t b0, uint32_t b1) {
    asm volatile("mma.sync.aligned.m16n8k16.row.col.f32.f16.f16.f32 "
                 "{%0,%1,%2,%3}, {%4,%5,%6,%7}, {%8,%9}, {%0,%1,%2,%3};"
                 : "+f"(c[0]), "+f"(c[1]), "+f"(c[2]), "+f"(c[3])
                 : "r"(a0), "r"(a1), "r"(a2), "r"(a3), "r"(b0), "r"(b1));
}
__device__ __forceinline__ void mma_tf32(float c[4], uint32_t a0, uint32_t a1,
                                         uint32_t a2, uint32_t a3,
                                         uint32_t b0, uint32_t b1) {
    asm volatile("mma.sync.aligned.m16n8k8.row.col.f32.tf32.tf32.f32 "
                 "{%0,%1,%2,%3}, {%4,%5,%6,%7}, {%8,%9}, {%0,%1,%2,%3};"
                 : "+f"(c[0]), "+f"(c[1]), "+f"(c[2]), "+f"(c[3])
                 : "r"(a0), "r"(a1), "r"(a2), "r"(a3), "r"(b0), "r"(b1));
}

// ============================================================================
// Kernel 1: tensor-core attention, f16 datapath. 32 queries per warp (two
// A-fragments sharing each key/value LDSM pair): halves LDSM traffic and
// doubles independent MMA/EX2 work per chain link (R14 was latency-bound).
// Grid = B*H*4 = 1024 CTAs, 256 threads; CTA covers 256 queries.
// No forced occupancy cap (R15's reg squeeze caused spills and regressed).
// ============================================================================
__global__ __launch_bounds__(256)
void qattn_mma(const float* __restrict__ x, const float* __restrict__ theta) {
    __shared__ __align__(16) __half Ps[T_][DK];
    __shared__ __align__(16) __half Pv[T_][DK];
    __shared__ float cth[DK];

    const int tid  = threadIdx.x;
    const int lane = tid & 31;
    const int warp = tid >> 5;
    const int qt   = blockIdx.x & 3;
    const int bh   = blockIdx.x >> 2;
    const int b    = bh >> 6;
    const int h    = bh & 63;

    if (tid < DK) cth[tid] = __cosf(theta[tid]);
    __syncthreads();

    const float S1 = 0.714215694f;  // sqrt((1/sqrt(8)) * log2(e))
    const float* xb = x + ((size_t)b * T_) * E_ + h * DK;
    #pragma unroll
    for (int i = 0; i < 4; i++) {
        int t = i * 256 + tid;
        float4 v0 = *(const float4*)(xb + (size_t)t * E_);
        float4 v1 = *(const float4*)(xb + (size_t)t * E_ + 4);
        float c[8];
        c[0] = __cosf(v0.x) * cth[0]; c[1] = __cosf(v0.y) * cth[1];
        c[2] = __cosf(v0.z) * cth[2]; c[3] = __cosf(v0.w) * cth[3];
        c[4] = __cosf(v1.x) * cth[4]; c[5] = __cosf(v1.y) * cth[5];
        c[6] = __cosf(v1.z) * cth[6]; c[7] = __cosf(v1.w) * cth[7];
        uint4 ps, pv;
        ps.x = h2p(S1 * c[0], S1 * c[1]); ps.y = h2p(S1 * c[2], S1 * c[3]);
        ps.z = h2p(S1 * c[4], S1 * c[5]); ps.w = h2p(S1 * c[6], S1 * c[7]);
        pv.x = h2p(c[0], c[1]); pv.y = h2p(c[2], c[3]);
        pv.z = h2p(c[4], c[5]); pv.w = h2p(c[6], c[7]);
        *(uint4*)&Ps[t][0] = ps;
        *(uint4*)&Pv[t][0] = pv;
    }
    __syncthreads();

    // Two query A-fragments per warp: rows qb0..+15 and qb0+16..+31.
    const int qb0 = qt * 256 + warp * 32;
    uint32_t qa0[2], qa1[2];
    ldsm_x2(qa0[0], qa1[0], smem_u32(&Ps[qb0 + (lane & 15)][0]));
    ldsm_x2(qa0[1], qa1[1], smem_u32(&Ps[qb0 + 16 + (lane & 15)][0]));

    float o[2][4] = {{0.f, 0.f, 0.f, 0.f}, {0.f, 0.f, 0.f, 0.f}};
    float l0[2] = {0.f, 0.f}, l1[2] = {0.f, 0.f};

    for (int k0 = 0; k0 < T_; k0 += 16) {
        uint32_t kb0, kb1, vb0, vb1;
        ldsm_x2(kb0, kb1, smem_u32(&Ps[k0 + (lane & 15)][0]));
        ldsm_x2t(vb0, vb1, smem_u32(&Pv[k0 + (lane & 15)][0]));

        #pragma unroll
        for (int w2 = 0; w2 < 2; w2++) {
            float c0[4] = {0.f, 0.f, 0.f, 0.f};
            float c1[4] = {0.f, 0.f, 0.f, 0.f};
            mma_k8h(c0, qa0[w2], qa1[w2], kb0);   // keys k0..k0+7
            mma_k8h(c1, qa0[w2], qa1[w2], kb1);   // keys k0+8..k0+15

            // scores -> f16x2 -> 2-wide EX2: results ARE the PV A-fragment.
            uint32_t p0 = ex2h2(h2p(c0[0], c0[1]));   // row r
            uint32_t p1 = ex2h2(h2p(c0[2], c0[3]));   // row r+8
            uint32_t p2 = ex2h2(h2p(c1[0], c1[1]));   // row r
            uint32_t p3 = ex2h2(h2p(c1[2], c1[3]));   // row r+8

            uint32_t s0 = hadd2(p0, p2);
            uint32_t s1 = hadd2(p1, p3);
            float2 f0 = __half22float2(*(__half2*)&s0);
            float2 f1 = __half22float2(*(__half2*)&s1);
            l0[w2] += f0.x + f0.y;
            l1[w2] += f1.x + f1.y;

            mma_k16h(o[w2], p0, p1, p2, p3, vb0, vb1);
        }
    }

    #pragma unroll
    for (int w2 = 0; w2 < 2; w2++) {
        float a = l0[w2], c = l1[w2];
        a += __shfl_xor_sync(0xFFFFFFFFu, a, 1);
        a += __shfl_xor_sync(0xFFFFFFFFu, a, 2);
        c += __shfl_xor_sync(0xFFFFFFFFu, c, 1);
        c += __shfl_xor_sync(0xFFFFFFFFu, c, 2);
        float inv0 = 1.0f / a, inv1 = 1.0f / c;

        const int q0 = qb0 + w2 * 16 + (lane >> 2);
        const int col = h * DK + ((lane & 3) << 1);
        float* p0o = g_attn + ((size_t)(b * T_ + q0)) * E_ + col;
        float* p1o = g_attn + ((size_t)(b * T_ + q0 + 8)) * E_ + col;
        *(float2*)p0o = make_float2(o[w2][0] * inv0, o[w2][1] * inv0);
        *(float2*)p1o = make_float2(o[w2][2] * inv1, o[w2][3] * inv1);
    }
}

// ============================================================================
// Kernel 2: tf32 combine GEMM — EXACT R10 body (proven 33us best).
// ============================================================================
#define PA_SZ 3328   // 8 mb * 2 kb * 208
#define PB_SZ 1088   // 8 nb * 2 kb * 68
__global__ __launch_bounds__(256)
void combine_tf32(const float* __restrict__ W, const float* __restrict__ bias,
                  float* __restrict__ C) {
    __shared__ __align__(16) uint32_t PA[2][PA_SZ];
    __shared__ __align__(16) uint32_t PB[2][PB_SZ];

    const int tid  = threadIdx.x;
    const int lane = tid & 31;
    const int warp = tid >> 5;
    const int g    = lane >> 2;
    const int tg   = lane & 3;
    const int row0 = blockIdx.y * 128;
    const int col0 = blockIdx.x * 64;
    const int mw   = warp >> 1;
    const int nw   = warp & 1;

    const int ar = tid >> 1, akb = tid & 1;
    const int wr = tid >> 2, wq = tid & 3;
    const int wkb = wq >> 1, wsel = wq & 1;
    const float* Ap = g_attn + (size_t)(row0 + ar) * E_ + akb * 8;
    const float* Wp = W      + (size_t)(col0 + wr) * E_ + wq * 4;

    const int a_base = ((ar >> 4) * 2 + akb) * 208 + ((ar >> 3) & 1) + (ar & 7) * 2;
    const int w_base = ((wr >> 3) * 2 + wkb) * 68 + (wr & 7) * 8 + wsel;

    float acc[2][4][4];
    #pragma unroll
    for (int mi = 0; mi < 2; mi++)
        #pragma unroll
        for (int ni = 0; ni < 4; ni++)
            #pragma unroll
            for (int j = 0; j < 4; j++) acc[mi][ni][j] = 0.f;

    float4 ra0 = *(const float4*)(Ap);
    float4 ra1 = *(const float4*)(Ap + 4);
    float4 rw  = *(const float4*)(Wp);

    {
        float av[8] = {ra0.x, ra0.y, ra0.z, ra0.w, ra1.x, ra1.y, ra1.z, ra1.w};
        #pragma unroll
        for (int j = 0; j < 8; j++) PA[0][a_base + j * 24] = tf32r(av[j]);
        float wv[4] = {rw.x, rw.y, rw.z, rw.w};
        #pragma unroll
        for (int j = 0; j < 4; j++) PB[0][w_base + j * 2] = tf32r(wv[j]);
    }
    __syncthreads();

    for (int ch = 0; ch < E_ / 16; ch++) {
        const int buf = ch & 1;
        const bool more = (ch + 1) < E_ / 16;
        if (more) {
            ra0 = *(const float4*)(Ap + (ch + 1) * 16);
            ra1 = *(const float4*)(Ap + (ch + 1) * 16 + 4);
            rw  = *(const float4*)(Wp + (ch + 1) * 16);
        }

        const uint32_t* pa = PA[buf];
        const uint32_t* pb = PB[buf];
        #pragma unroll
        for (int kb = 0; kb < 2; kb++) {
            ull ap1[2], ap2[2], bp[4];
            #pragma unroll
            for (int mi = 0; mi < 2; mi++) {
                int ab = ((2 * mw + mi) * 2 + kb) * 208 + tg * 24 + g * 2;
                ap1[mi] = *(const ull*)&pa[ab];
                ap2[mi] = *(const ull*)&pa[ab + 96];
            }
            #pragma unroll
            for (int ni = 0; ni < 4; ni++) {
                int bb = ((4 * nw + ni) * 2 + kb) * 68 + g * 8 + tg * 2;
                bp[ni] = *(const ull*)&pb[bb];
            }
            #pragma unroll
            for (int ni = 0; ni < 4; ni++) {
                uint32_t b0 = (uint32_t)bp[ni], b1 = (uint32_t)(bp[ni] >> 32);
                #pragma unroll
                for (int mi = 0; mi < 2; mi++) {
                    uint32_t a0 = (uint32_t)ap1[mi], a1 = (uint32_t)(ap1[mi] >> 32);
                    uint32_t a2 = (uint32_t)ap2[mi], a3 = (uint32_t)(ap2[mi] >> 32);
                    mma_tf32(acc[mi][ni], a0, a1, a2, a3, b0, b1);
                }
            }
        }

        if (more) {
            const int nb = buf ^ 1;
            float av[8] = {ra0.x, ra0.y, ra0.z, ra0.w, ra1.x, ra1.y, ra1.z, ra1.w};
            #pragma unroll
            for (int j = 0; j < 8; j++) PA[nb][a_base + j * 24] = tf32r(av[j]);
            float wv[4] = {rw.x, rw.y, rw.z, rw.w};
            #pragma unroll
            for (int j = 0; j < 4; j++) PB[nb][w_base + j * 2] = tf32r(wv[j]);
        }
        __syncthreads();
    }

    #pragma unroll
    for (int mi = 0; mi < 2; mi++) {
        int row = row0 + mw * 32 + mi * 16 + g;
        #pragma unroll
        for (int ni = 0; ni < 4; ni++) {
            int c = col0 + nw * 32 + ni * 8 + (tg << 1);
            float2 bi = *(const float2*)&bias[c];
            *(float2*)&C[(size_t)row * E_ + c] =
                make_float2(acc[mi][ni][0] + bi.x, acc[mi][ni][1] + bi.y);
            *(float2*)&C[(size_t)(row + 8) * E_ + c] =
                make_float2(acc[mi][ni][2] + bi.x, acc[mi][ni][3] + bi.y);
        }
    }
}

extern "C" void kernel_launch(void* const* d_in, const int* in_sizes, int n_in,
                              void* d_out, int out_size) {
    const float* x     = (const float*)d_in[0];
    const float* theta = (const float*)d_in[1];
    const float* W     = (const float*)d_in[2];
    const float* bias  = (const float*)d_in[3];
    float* out = (float*)d_out;

    qattn_mma<<<B_ * H_ * 4, 256>>>(x, theta);
    dim3 g2(E_ / 64, (B_ * T_) / 128);
    combine_tf32<<<g2, 256>>>(W, bias, out);
}